// round 4
// baseline (speedup 1.0000x reference)
#include <cuda_runtime.h>
#include <math.h>

// ---------------------------------------------------------------------------
// DCRNN (PEMS-BAY) forward: encoder 12 steps x 2 DCGRU layers, decoder 12 x 2.
// All state kept in (N, B, F) layout so the graph diffusion 'mn,bnf->bmf'
// is a single dense GEMM  Lstack(650x325) @ X(325 x B*F), where
// Lstack = [L ; 2*L^2] produces Chebyshev x1 and (x2 + x0) in one shot.
// ---------------------------------------------------------------------------

#define NN     325
#define BB     64
#define UU     64
#define TSTEPS 12
#define HSTEPS 12
#define RR     (NN*BB)      /* 20800 rows (n*B + b) */
#define FMAX   128
#define MST    (2*NN)       /* 650 stacked rows of Lstack */

typedef unsigned long long ull;

// ------------------------- device scratch (static) -------------------------
__device__ float g_L2[MST*NN];      // [L ; 2 L^2], row major 650 x 325
__device__ float g_h0[RR*UU];       // layer-0 hidden (enc then dec)
__device__ float g_h1[RR*UU];       // layer-1 hidden
__device__ float g_Xc[RR*FMAX];     // concat [x, h] in (N,B,F)
__device__ float g_X1[RR*FMAX];     // L @ Xc
__device__ float g_X2[RR*FMAX];     // 2 L^2 @ Xc - Xc
__device__ float g_u [RR*UU];       // update gate
__device__ float g_rh[RR*UU];       // r * h
__device__ float g_din[RR];         // decoder input (DOUT=1), (N,B)

// ------------------------- f32x2 packed-FMA helpers ------------------------
__device__ __forceinline__ ull pk2(float lo, float hi) {
    ull r; asm("mov.b64 %0, {%1,%2};" : "=l"(r) : "f"(lo), "f"(hi)); return r;
}
__device__ __forceinline__ void upk2(ull v, float &lo, float &hi) {
    asm("mov.b64 {%0,%1}, %2;" : "=f"(lo), "=f"(hi) : "l"(v));
}
__device__ __forceinline__ void fma2(ull &d, ull a, ull b) {
    asm("fma.rn.f32x2 %0, %1, %2, %0;" : "+l"(d) : "l"(a), "l"(b));
}

// --------------------- Lstack = [L ; 2 L^2] (once/launch) ------------------
__global__ void k_lstack(const float* __restrict__ S) {
    int idx = blockIdx.x * blockDim.x + threadIdx.x;
    if (idx >= MST*NN) return;
    int m = idx / NN, n = idx % NN;
    if (m < NN) {
        g_L2[idx] = S[idx];
    } else {
        int mm = m - NN;
        float s = 0.f;
        for (int k = 0; k < NN; k++) s += S[mm*NN + k] * S[k*NN + n];
        g_L2[idx] = 2.0f * s;
    }
}

// ------------------------------ state init --------------------------------
__global__ void k_zero() {
    int i = blockIdx.x * blockDim.x + threadIdx.x;
    if (i < RR*UU) { g_h0[i] = 0.f; g_h1[i] = 0.f; }
    if (i < RR)    g_din[i] = 0.f;
}

// ----------------- pack Xc = concat([x, h_or_rh]) in (N,B,F) ---------------
// xsel: 0 = external pointer (encoder inputs), 1 = g_h0, 2 = g_din
// hsel: 0 = g_h0, 1 = g_h1, 2 = g_rh
__global__ void k_pack(const float* __restrict__ xext, int xsel,
                       int xn_str, int xb_str, int xF, int F,
                       int hsel, int write_x, int total) {
    const float* xs = (xsel == 1) ? g_h0 : (xsel == 2) ? g_din : xext;
    const float* hs = (hsel == 0) ? g_h0 : (hsel == 1) ? g_h1 : g_rh;
    for (int i = blockIdx.x * blockDim.x + threadIdx.x; i < total;
         i += gridDim.x * blockDim.x) {
        int f  = i % F;
        int nb = i / F;
        if (f < xF) {
            if (write_x) {
                int b = nb % BB, n = nb / BB;
                g_Xc[i] = xs[n * xn_str + b * xb_str + f];
            }
        } else {
            g_Xc[i] = hs[nb * UU + (f - xF)];
        }
    }
}

// ------- SpMM: [X1; X2+Xc] = Lstack(650x325) @ Xc(325 x J), J = B*F --------
// Tiles: BM=64 (m), BN=128 (j), BK=16; 256 threads, micro-tile 4x8 (f32x2).
__global__ __launch_bounds__(256) void k_spmm(int J) {
    __shared__ __align__(16) float As[16][68];    // [k][m], padded vs bank conflicts
    __shared__ __align__(16) float Bs[16][128];   // [k][j]
    const int tid = threadIdx.x;
    const int m0 = blockIdx.y * 64;
    const int j0 = blockIdx.x * 128;
    const int tx = tid % 16, ty = tid / 16;

    ull acc[4][4];
    #pragma unroll
    for (int i = 0; i < 4; i++)
        #pragma unroll
        for (int j = 0; j < 4; j++) acc[i][j] = 0ULL;

    for (int k0 = 0; k0 < NN; k0 += 16) {
        #pragma unroll
        for (int e = 0; e < 4; e++) {               // A tile 64x16
            int idx = tid + e * 256;
            int r = idx / 16, c = idx % 16;
            int mg = m0 + r, kg = k0 + c;
            As[c][r] = (mg < MST && kg < NN) ? g_L2[mg*NN + kg] : 0.f;
        }
        #pragma unroll
        for (int e = 0; e < 8; e++) {               // B tile 16x128
            int idx = tid + e * 256;
            int r = idx / 128, c = idx % 128;
            int kg = k0 + r, jg = j0 + c;
            Bs[r][c] = (kg < NN && jg < J) ? g_Xc[kg*J + jg] : 0.f;
        }
        __syncthreads();
        #pragma unroll
        for (int k = 0; k < 16; k++) {
            const ull* brow = (const ull*)&Bs[k][0];
            ull b[4];
            #pragma unroll
            for (int j = 0; j < 4; j++) b[j] = brow[tx*4 + j];
            #pragma unroll
            for (int i = 0; i < 4; i++) {
                float av = As[k][ty*4 + i];
                ull a2 = pk2(av, av);
                #pragma unroll
                for (int j = 0; j < 4; j++) fma2(acc[i][j], a2, b[j]);
            }
        }
        __syncthreads();
    }

    #pragma unroll
    for (int i = 0; i < 4; i++) {
        int mg = m0 + ty*4 + i;
        if (mg >= MST) continue;
        #pragma unroll
        for (int j = 0; j < 4; j++) {
            float lo, hi; upk2(acc[i][j], lo, hi);
            int jg = j0 + tx*8 + 2*j;
            if (mg < NN) {
                if (jg     < J) g_X1[mg*J + jg]     = lo;
                if (jg + 1 < J) g_X1[mg*J + jg + 1] = hi;
            } else {
                int mm = mg - NN;
                if (jg     < J) g_X2[mm*J + jg]     = lo - g_Xc[mm*J + jg];
                if (jg + 1 < J) g_X2[mm*J + jg + 1] = hi - g_Xc[mm*J + jg + 1];
            }
        }
    }
}

// --------- weight GEMM: out = act([Xc|X1|X2](RR x 3F) @ W(3F x OD)) --------
// mode 0 (gate, OD=128): v=sigmoid; o<U -> rh = v*h ; o>=U -> u = v
// mode 1 (cand, OD=64):  c=tanh;  h = u*h + (1-u)*c   (in place)
// Tiles: BM=64 (RR%64==0), BN=64, BK=16; 256 threads, micro-tile 4x4.
__global__ __launch_bounds__(256) void k_wgemm(const float* __restrict__ W,
                                               const float* __restrict__ bias,
                                               int F, int OD, int mode, int hsel) {
    __shared__ __align__(16) float As[16][68];
    __shared__ __align__(16) float Bs[16][64];
    const int tid = threadIdx.x;
    const int r0 = blockIdx.x * 64;
    const int o0 = blockIdx.y * 64;
    const int tx = tid % 16, ty = tid / 16;

    ull acc[4][2];
    #pragma unroll
    for (int i = 0; i < 4; i++) { acc[i][0] = 0ULL; acc[i][1] = 0ULL; }

    for (int s = 0; s < 3; s++) {
        const float* A = (s == 0) ? g_Xc : (s == 1) ? g_X1 : g_X2;
        for (int k0 = 0; k0 < F; k0 += 16) {
            #pragma unroll
            for (int e = 0; e < 4; e++) {           // A tile 64x16
                int idx = tid + e * 256;
                int r = idx / 16, c = idx % 16;
                As[c][r] = (k0 + c < F) ? A[(r0 + r)*F + k0 + c] : 0.f;
            }
            #pragma unroll
            for (int e = 0; e < 4; e++) {           // W tile 16x64
                int idx = tid + e * 256;
                int r = idx / 64, c = idx % 64;
                int kg = k0 + r;
                Bs[r][c] = (kg < F) ? W[(s*F + kg)*OD + o0 + c] : 0.f;
            }
            __syncthreads();
            #pragma unroll
            for (int k = 0; k < 16; k++) {
                const ull* brow = (const ull*)&Bs[k][0];
                ull b0 = brow[tx*2], b1 = brow[tx*2 + 1];
                #pragma unroll
                for (int i = 0; i < 4; i++) {
                    float av = As[k][ty*4 + i];
                    ull a2 = pk2(av, av);
                    fma2(acc[i][0], a2, b0);
                    fma2(acc[i][1], a2, b1);
                }
            }
            __syncthreads();
        }
    }

    float* h = hsel ? g_h1 : g_h0;
    #pragma unroll
    for (int i = 0; i < 4; i++) {
        int r = r0 + ty*4 + i;
        #pragma unroll
        for (int j2 = 0; j2 < 2; j2++) {
            float lo, hi; upk2(acc[i][j2], lo, hi);
            int o = o0 + tx*4 + 2*j2;
            #pragma unroll
            for (int p = 0; p < 2; p++) {
                float v = (p == 0 ? lo : hi) + bias[o + p];
                int og = o + p;
                if (mode == 0) {
                    float sg = 1.0f / (1.0f + expf(-v));
                    if (og < UU) g_rh[r*UU + og] = sg * h[r*UU + og];
                    else         g_u [r*UU + og - UU] = sg;
                } else {
                    float c = tanhf(v);
                    int idx = r*UU + og;
                    float uu = g_u[idx];
                    h[idx] = uu * h[idx] + (1.0f - uu) * c;
                }
            }
        }
    }
}

// --------- projection: out[b*N+n] = h1[n,b,:] . pW + pb; also -> g_din -----
__global__ void k_proj(const float* __restrict__ pW, const float* __restrict__ pb,
                       float* __restrict__ outp) {
    int gid = blockIdx.x * blockDim.x + threadIdx.x;
    int row = gid >> 5, lane = gid & 31;
    if (row >= RR) return;
    float s = g_h1[row*UU + lane] * pW[lane]
            + g_h1[row*UU + lane + 32] * pW[lane + 32];
    #pragma unroll
    for (int off = 16; off; off >>= 1) s += __shfl_down_sync(0xffffffffu, s, off);
    if (lane == 0) {
        float v = s + pb[0];
        int n = row / BB, b = row % BB;
        outp[b*NN + n] = v;
        g_din[row] = v;
    }
}

// ------------------------------- host side ---------------------------------
static void run_cell(const float* xext, int xsel, int xn_str, int xb_str,
                     int xF, int F, int hsel,
                     const float* gW, const float* gb,
                     const float* cW, const float* cb) {
    const int total = RR * F;
    const int J = BB * F;
    dim3 gs((J + 127) / 128, (MST + 63) / 64);
    dim3 gg(RR / 64, 2);   // gate OD=128
    dim3 gc(RR / 64, 1);   // cand OD=64
    int pb = (total + 255) / 256;

    // gate path
    k_pack <<<pb, 256>>>(xext, xsel, xn_str, xb_str, xF, F, hsel, 1, total);
    k_spmm <<<gs, 256>>>(J);
    k_wgemm<<<gg, 256>>>(gW, gb, F, 128, /*mode=*/0, hsel);
    // candidate path (x part of Xc is already in place; refresh h-part = r*h)
    k_pack <<<pb, 256>>>(xext, xsel, xn_str, xb_str, xF, F, /*hsel=*/2, 0, total);
    k_spmm <<<gs, 256>>>(J);
    k_wgemm<<<gc, 256>>>(cW, cb, F, 64, /*mode=*/1, hsel);
}

extern "C" void kernel_launch(void* const* d_in, const int* in_sizes, int n_in,
                              void* d_out, int out_size) {
    const float* inputs  = (const float*)d_in[0];
    const float* support = (const float*)d_in[1];
    const float* W[16];
    for (int i = 0; i < 16; i++) W[i] = (const float*)d_in[2 + i];
    const float* projW = (const float*)d_in[18];
    const float* projb = (const float*)d_in[19];
    float* out = (float*)d_out;

    k_lstack<<<(MST*NN + 255) / 256, 256>>>(support);
    k_zero  <<<(RR*UU + 255) / 256, 256>>>();

    // encoder: 12 steps, 2 layers
    for (int t = 0; t < TSTEPS; t++) {
        const float* xt = inputs + (size_t)t * BB * NN * 2;   // (B, N, 2)
        run_cell(xt,      0, /*xn*/2,      /*xb*/NN*2, /*xF*/2,  /*F*/66,  /*h*/0,
                 W[0], W[1], W[2], W[3]);                      // enc layer 0
        run_cell(nullptr, 1, /*xn*/BB*UU,  /*xb*/UU,   /*xF*/64, /*F*/128, /*h*/1,
                 W[4], W[5], W[6], W[7]);                      // enc layer 1
    }
    // decoder: 12 steps, 2 layers + projection (feeds next input)
    for (int t = 0; t < HSTEPS; t++) {
        run_cell(nullptr, 2, /*xn*/BB,     /*xb*/1,    /*xF*/1,  /*F*/65,  /*h*/0,
                 W[8],  W[9],  W[10], W[11]);                  // dec layer 0
        run_cell(nullptr, 1, /*xn*/BB*UU,  /*xb*/UU,   /*xF*/64, /*F*/128, /*h*/1,
                 W[12], W[13], W[14], W[15]);                  // dec layer 1
        k_proj<<<(RR*32 + 255) / 256, 256>>>(projW, projb, out + (size_t)t * BB * NN);
    }
}

// round 9
// speedup vs baseline: 1.3353x; 1.3353x over previous
#include <cuda_runtime.h>
#include <math.h>

// ---------------------------------------------------------------------------
// DCRNN forward. State kept in (N, B, F) layout throughout so:
//   * graph diffusion = dense GEMM  Lstack(650x325) @ X(325 x B*F)
//   * hidden h (N,B,U) IS the h-part of the gconv input -> zero packing
//   * candidate gconv reuses the gate gconv's diffusion of the x-columns
// Lstack = [S ; 2*S^2] padded to 704 x 336 (aligned, guard-free k-loop).
// ---------------------------------------------------------------------------

#define NN     325
#define BB     64
#define UU     64
#define TSTEPS 12
#define HSTEPS 12
#define RR     (NN*BB)      /* 20800 */
#define MST    (2*NN)       /* 650 */
#define LDK    336          /* padded K stride of Lstack */
#define MP     704          /* padded M of Lstack */
#define NKT    (LDK/16)     /* 21 k-tiles */
#define JHH    (BB*UU)      /* 4096 h-part columns */
#define NPADR  336          /* padded input rows (>= LDK) */

typedef unsigned long long ull;

// ------------------------- device scratch ----------------------------------
__device__ float g_L2 [MP*LDK];      // [S ; 2 S^2], padded
__device__ float g_h0 [NPADR*JHH];   // layer-0 hidden, rows >=325 stay zero
__device__ float g_h1 [NPADR*JHH];   // layer-1 hidden
__device__ float g_rh [NPADR*JHH];   // r * h
__device__ float g_xx [NPADR*128];   // encoder x packed (N, B*2)
__device__ float g_din[NPADR*64];    // decoder input (N, B)
__device__ float g_X1x[NN*JHH];      // S  @ x-part
__device__ float g_X2x[NN*JHH];      // (2S^2 - I) @ x-part
__device__ float g_X1h[NN*JHH];      // S  @ h-part
__device__ float g_X2h[NN*JHH];
__device__ float g_u  [RR*UU];       // update gate

// ------------------------- f32x2 helpers -----------------------------------
__device__ __forceinline__ ull pk2(float lo, float hi) {
    ull r; asm("mov.b64 %0, {%1,%2};" : "=l"(r) : "f"(lo), "f"(hi)); return r;
}
__device__ __forceinline__ void upk2(ull v, float &lo, float &hi) {
    asm("mov.b64 {%0,%1}, %2;" : "=f"(lo), "=f"(hi) : "l"(v));
}
__device__ __forceinline__ void fma2(ull &d, ull a, ull b) {
    asm("fma.rn.f32x2 %0, %1, %2, %0;" : "+l"(d) : "l"(a), "l"(b));
}

// --------------------- Lstack (once per launch) ----------------------------
__global__ void k_lstack(const float* __restrict__ S) {
    int idx = blockIdx.x * blockDim.x + threadIdx.x;
    if (idx >= MP*LDK) return;
    int m = idx / LDK, n = idx % LDK;
    float v = 0.f;
    if (n < NN) {
        if (m < NN) {
            v = S[m*NN + n];
        } else if (m < MST) {
            int mm = m - NN;
            float s = 0.f;
            for (int k = 0; k < NN; k++) s += S[mm*NN + k] * S[k*NN + n];
            v = 2.0f * s;
        }
    }
    g_L2[idx] = v;
}

// ------------------------------ state init ---------------------------------
__global__ void k_zero() {
    int i = blockIdx.x * blockDim.x + threadIdx.x;
    int st = gridDim.x * blockDim.x;
    for (int j = i; j < NPADR*JHH; j += st) { g_h0[j] = 0.f; g_h1[j] = 0.f; g_rh[j] = 0.f; }
    for (int j = i; j < NPADR*128; j += st) g_xx[j]  = 0.f;
    for (int j = i; j < NPADR*64;  j += st) g_din[j] = 0.f;
}

// --------------- encoder input transpose (B,N,2) -> (N, B*2) ---------------
__global__ void k_pack_enc(const float* __restrict__ x) {
    int i = blockIdx.x * blockDim.x + threadIdx.x;
    if (i >= NN*128) return;
    int n = i >> 7, c = i & 127;        // c = b*2 + f
    int b = c >> 1, f = c & 1;
    g_xx[i] = x[(b*NN + n)*2 + f];
}

// --------------- stacked diffusion SpMM ------------------------------------
// Lstack(704x336 padded) @ Xpart(336 x J).  Block tile 64(m) x 128(j), BK=16,
// 256 threads, micro 4x8 via f32x2, register-staged double buffering.
// Grid.x = nbx (x-part block cols) + 32 (h-part).  Grid.y = 11.
__global__ __launch_bounds__(256, 2) void k_spmm(int axsel, int Jx, int nbx, int ahsel)
{
    __shared__ __align__(16) float As[2][16][68];
    __shared__ __align__(16) float Bs[2][16][128];

    const float* Ain; int J, j0; float *O1, *O2;
    int bx = blockIdx.x;
    if (bx < nbx) {
        Ain = (axsel == 0) ? g_xx : (axsel == 1) ? g_h0 : g_din;
        J = Jx; j0 = bx * 128; O1 = g_X1x; O2 = g_X2x;
    } else {
        Ain = (ahsel == 0) ? g_h0 : (ahsel == 1) ? g_h1 : g_rh;
        J = JHH; j0 = (bx - nbx) * 128; O1 = g_X1h; O2 = g_X2h;
    }
    const int tid = threadIdx.x;
    const int m0  = blockIdx.y * 64;
    const int tx  = tid & 15, ty = tid >> 4;
    const int arow = tid >> 2, akq = tid & 3;       // A stage: 1 float4/thread

    float4 sa; float4 sb[2];
    ull acc[4][4];
    #pragma unroll
    for (int i = 0; i < 4; i++)
        #pragma unroll
        for (int j = 0; j < 4; j++) acc[i][j] = 0ULL;

    auto gload = [&](int t) {
        int k0 = t * 16;
        sa = *(const float4*)&g_L2[(m0 + arow)*LDK + k0 + akq*4];
        #pragma unroll
        for (int e = 0; e < 2; e++) {
            int idx = tid + e*256;
            int r = idx >> 5, c4 = idx & 31;
            int jg = j0 + c4*4;
            const float* p = &Ain[(k0 + r)*J + jg];
            if (jg + 3 < J) sb[e] = *(const float4*)p;
            else {
                float4 z = {0.f,0.f,0.f,0.f};
                if (jg     < J) z.x = p[0];
                if (jg + 1 < J) z.y = p[1];
                if (jg + 2 < J) z.z = p[2];
                if (jg + 3 < J) z.w = p[3];
                sb[e] = z;
            }
        }
    };
    auto gstore = [&](int buf) {
        As[buf][akq*4+0][arow] = sa.x;
        As[buf][akq*4+1][arow] = sa.y;
        As[buf][akq*4+2][arow] = sa.z;
        As[buf][akq*4+3][arow] = sa.w;
        #pragma unroll
        for (int e = 0; e < 2; e++) {
            int idx = tid + e*256;
            int r = idx >> 5, c4 = idx & 31;
            *(float4*)&Bs[buf][r][c4*4] = sb[e];
        }
    };

    gload(0); gstore(0); __syncthreads();
    for (int t = 0; t < NKT; t++) {
        int cur = t & 1;
        if (t + 1 < NKT) gload(t + 1);
        #pragma unroll
        for (int k = 0; k < 16; k++) {
            float4 a4 = *(const float4*)&As[cur][k][ty*4];
            ulonglong2 q0 = *(const ulonglong2*)&Bs[cur][k][tx*8];
            ulonglong2 q1 = *(const ulonglong2*)&Bs[cur][k][tx*8 + 4];
            ull a0 = pk2(a4.x, a4.x), a1 = pk2(a4.y, a4.y);
            ull a2 = pk2(a4.z, a4.z), a3 = pk2(a4.w, a4.w);
            fma2(acc[0][0],a0,q0.x); fma2(acc[0][1],a0,q0.y); fma2(acc[0][2],a0,q1.x); fma2(acc[0][3],a0,q1.y);
            fma2(acc[1][0],a1,q0.x); fma2(acc[1][1],a1,q0.y); fma2(acc[1][2],a1,q1.x); fma2(acc[1][3],a1,q1.y);
            fma2(acc[2][0],a2,q0.x); fma2(acc[2][1],a2,q0.y); fma2(acc[2][2],a2,q1.x); fma2(acc[2][3],a2,q1.y);
            fma2(acc[3][0],a3,q0.x); fma2(acc[3][1],a3,q0.y); fma2(acc[3][2],a3,q1.x); fma2(acc[3][3],a3,q1.y);
        }
        if (t + 1 < NKT) gstore((t + 1) & 1);
        __syncthreads();
    }

    #pragma unroll
    for (int i = 0; i < 4; i++) {
        int mg = m0 + ty*4 + i;
        if (mg >= MST) continue;
        #pragma unroll
        for (int j = 0; j < 4; j++) {
            float lo, hi; upk2(acc[i][j], lo, hi);
            int jg = j0 + tx*8 + 2*j;
            if (mg < NN) {
                if (jg     < J) O1[mg*J + jg]     = lo;
                if (jg + 1 < J) O1[mg*J + jg + 1] = hi;
            } else {
                int mm = mg - NN;
                if (jg     < J) O2[mm*J + jg]     = lo - Ain[mm*J + jg];
                if (jg + 1 < J) O2[mm*J + jg + 1] = hi - Ain[mm*J + jg + 1];
            }
        }
    }
}

// --------------- weight GEMM over 6 K-segments + fused GRU epilogue --------
// A = [x | h | S@x | S@h | (2S^2-I)@x | (2S^2-I)@h] (RR x 3F), W(3F x OD).
// mode 0 (gate, OD=128): sigmoid; o<U -> rh = r*h ; o>=U -> u.
// mode 1 (cand, OD=64):  tanh;    h = u*h + (1-u)*c (in place).
__global__ __launch_bounds__(256, 3) void k_wgemm(
    const float* __restrict__ W, const float* __restrict__ bias,
    int xF, int OD, int mode, int axsel, int phsel, int uh)
{
    __shared__ __align__(16) float As[16][68];
    __shared__ __align__(16) float Bs[16][64];
    const float* px = (axsel == 0) ? g_xx : (axsel == 1) ? g_h0 : g_din;
    const float* ph = (phsel == 0) ? g_h0 : (phsel == 1) ? g_h1 : g_rh;
    float* h = uh ? g_h1 : g_h0;
    const int F = xF + UU;
    const int tid = threadIdx.x;
    const int r0 = blockIdx.x * 64, o0 = blockIdx.y * 64;
    const int tx = tid & 15, ty = tid >> 4;

    ull acc[4][2];
    #pragma unroll
    for (int i = 0; i < 4; i++) { acc[i][0] = 0ULL; acc[i][1] = 0ULL; }

    #pragma unroll 1
    for (int s = 0; s < 6; s++) {
        const float* A; int K, wr;
        switch (s) {
            case 0:  A = px;     K = xF; wr = 0;        break;
            case 1:  A = ph;     K = UU; wr = xF;       break;
            case 2:  A = g_X1x;  K = xF; wr = F;        break;
            case 3:  A = g_X1h;  K = UU; wr = F + xF;   break;
            case 4:  A = g_X2x;  K = xF; wr = 2*F;      break;
            default: A = g_X2h;  K = UU; wr = 2*F + xF; break;
        }
        for (int k0 = 0; k0 < K; k0 += 16) {
            if (K == UU) {                        // vector A load (K=64)
                int row = tid >> 2, kq = tid & 3;
                float4 v = *(const float4*)&A[(r0 + row)*UU + k0 + kq*4];
                As[kq*4+0][row] = v.x; As[kq*4+1][row] = v.y;
                As[kq*4+2][row] = v.z; As[kq*4+3][row] = v.w;
            } else {                               // K in {1,2}: guarded
                #pragma unroll
                for (int e = 0; e < 4; e++) {
                    int idx = tid + e*256;
                    int r = idx >> 4, k = idx & 15;
                    As[k][r] = (k < K) ? A[(r0 + r)*K + k] : 0.f;
                }
            }
            {
                int row = tid >> 4, c4 = tid & 15;
                float4 v = {0.f,0.f,0.f,0.f};
                if (k0 + row < K) v = *(const float4*)&W[(wr + k0 + row)*OD + o0 + c4*4];
                *(float4*)&Bs[row][c4*4] = v;
            }
            __syncthreads();
            #pragma unroll
            for (int k = 0; k < 16; k++) {
                float4 a4 = *(const float4*)&As[k][ty*4];
                ulonglong2 b = *(const ulonglong2*)&Bs[k][tx*4];
                ull a0 = pk2(a4.x, a4.x), a1 = pk2(a4.y, a4.y);
                ull a2 = pk2(a4.z, a4.z), a3 = pk2(a4.w, a4.w);
                fma2(acc[0][0],a0,b.x); fma2(acc[0][1],a0,b.y);
                fma2(acc[1][0],a1,b.x); fma2(acc[1][1],a1,b.y);
                fma2(acc[2][0],a2,b.x); fma2(acc[2][1],a2,b.y);
                fma2(acc[3][0],a3,b.x); fma2(acc[3][1],a3,b.y);
            }
            __syncthreads();
        }
    }

    #pragma unroll
    for (int i = 0; i < 4; i++) {
        int r = r0 + ty*4 + i;
        #pragma unroll
        for (int j2 = 0; j2 < 2; j2++) {
            float lo, hi; upk2(acc[i][j2], lo, hi);
            #pragma unroll
            for (int p = 0; p < 2; p++) {
                int og = o0 + tx*4 + 2*j2 + p;
                float v = (p ? hi : lo) + bias[og];
                if (mode == 0) {
                    float sg = 1.0f / (1.0f + expf(-v));
                    if (og < UU) g_rh[r*UU + og] = sg * h[r*UU + og];
                    else         g_u [r*UU + og - UU] = sg;
                } else {
                    float c = tanhf(v);
                    int idx = r*UU + og;
                    float u = g_u[idx];
                    h[idx] = u * h[idx] + (1.0f - u) * c;
                }
            }
        }
    }
}

// --------- projection: out[b*N+n] = h1[n,b,:] . pW + pb; also -> g_din -----
__global__ void k_proj(const float* __restrict__ pW, const float* __restrict__ pb,
                       float* __restrict__ outp) {
    int gid = blockIdx.x * blockDim.x + threadIdx.x;
    int row = gid >> 5, lane = gid & 31;
    if (row >= RR) return;
    float s = g_h1[row*UU + lane] * pW[lane]
            + g_h1[row*UU + lane + 32] * pW[lane + 32];
    #pragma unroll
    for (int off = 16; off; off >>= 1) s += __shfl_down_sync(0xffffffffu, s, off);
    if (lane == 0) {
        float v = s + pb[0];
        int n = row / BB, b = row % BB;
        outp[b*NN + n] = v;
        g_din[row] = v;
    }
}

// ------------------------------- host side ---------------------------------
static void run_cell(int xF, int axsel, int uh,
                     const float* gW, const float* gb,
                     const float* cW, const float* cb) {
    int Jx  = BB * xF;
    int nbx = (Jx + 127) / 128;
    // gate: diffuse x-part once + h-part
    k_spmm <<<dim3(nbx + 32, 11), 256>>>(axsel, Jx, nbx, uh);
    k_wgemm<<<dim3(RR/64, 2), 256>>>(gW, gb, xF, 128, /*mode=*/0, axsel, uh, uh);
    // candidate: diffuse only r*h (x diffusion reused)
    k_spmm <<<dim3(32, 11), 256>>>(0, 0, 0, /*ahsel=rh*/2);
    k_wgemm<<<dim3(RR/64, 1), 256>>>(cW, cb, xF, 64, /*mode=*/1, axsel, 2, uh);
}

extern "C" void kernel_launch(void* const* d_in, const int* in_sizes, int n_in,
                              void* d_out, int out_size) {
    const float* inputs  = (const float*)d_in[0];
    const float* support = (const float*)d_in[1];
    const float* W[16];
    for (int i = 0; i < 16; i++) W[i] = (const float*)d_in[2 + i];
    const float* projW = (const float*)d_in[18];
    const float* projb = (const float*)d_in[19];
    float* out = (float*)d_out;

    k_lstack<<<(MP*LDK + 255) / 256, 256>>>(support);
    k_zero  <<<592, 256>>>();

    for (int t = 0; t < TSTEPS; t++) {
        k_pack_enc<<<(NN*128 + 255) / 256, 256>>>(inputs + (size_t)t * BB * NN * 2);
        run_cell(2,  /*axsel=g_xx*/0, /*h=*/0, W[0],  W[1],  W[2],  W[3]);   // enc L0
        run_cell(64, /*axsel=g_h0*/1, /*h=*/1, W[4],  W[5],  W[6],  W[7]);   // enc L1
    }
    for (int t = 0; t < HSTEPS; t++) {
        run_cell(1,  /*axsel=din*/2,  /*h=*/0, W[8],  W[9],  W[10], W[11]);  // dec L0
        run_cell(64, /*axsel=g_h0*/1, /*h=*/1, W[12], W[13], W[14], W[15]);  // dec L1
        k_proj<<<(RR*32 + 255) / 256, 256>>>(projW, projb, out + (size_t)t * BB * NN);
    }
}

// round 10
// speedup vs baseline: 1.9688x; 1.4744x over previous
#include <cuda_runtime.h>
#include <math.h>

// ---------------------------------------------------------------------------
// DCRNN forward, sparse-diffusion edition.
//   * support S = L - I is ~2% dense; 2*S^2 ~13%. Dense 650x325 diffusion GEMM
//     replaced by device-built padded CSR + sparse SpMM with smem-cached X tile.
//   * state kept in (N, B, F) layout: h IS the gconv h-input, no packing.
//   * candidate gconv reuses the gate gconv's diffusion of the x-columns.
//   * weight GEMM: 128xOD blocks, 8x8 / 8x4 f32x2 micro-tiles, fused GRU math.
// ---------------------------------------------------------------------------

#define NN     325
#define BB     64
#define UU     64
#define TSTEPS 12
#define HSTEPS 12
#define RR     (NN*BB)      /* 20800 */
#define MST    (2*NN)       /* 650 */
#define LDK    336          /* padded col stride of dense Lstack scratch */
#define JHH    (BB*UU)      /* 4096 */
#define NPADR  336
#define CSRCAP (650*328)    /* worst-case padded nnz */
#define WGB    ((RR + 127) / 128)   /* 163 row-blocks for weight GEMM */

typedef unsigned long long ull;

// ------------------------- device scratch ----------------------------------
__device__ float g_L2 [MST*LDK];     // dense [S ; 2 S^2] (CSR build scratch)
__device__ __align__(16) float g_vals[CSRCAP];
__device__ __align__(16) int   g_cols[CSRCAP];
__device__ int   g_rp  [MST + 1];
__device__ int   g_cnt [MST];
__device__ float g_h0 [NPADR*JHH];
__device__ float g_h1 [NPADR*JHH];
__device__ float g_rh [NPADR*JHH];   // r * h
__device__ float g_xx [NPADR*128];   // encoder x packed (N, B*2)
__device__ float g_din[NPADR*64];    // decoder input (N, B)
__device__ float g_X1x[NN*JHH];      // S @ x-part
__device__ float g_X2x[NN*JHH];      // (2S^2 - I) @ x-part
__device__ float g_X1h[NN*JHH];      // S @ h-part
__device__ float g_X2h[NN*JHH];
__device__ float g_u  [RR*UU];       // update gate

// ------------------------- f32x2 helpers -----------------------------------
__device__ __forceinline__ ull pk2(float lo, float hi) {
    ull r; asm("mov.b64 %0, {%1,%2};" : "=l"(r) : "f"(lo), "f"(hi)); return r;
}
__device__ __forceinline__ void upk2(ull v, float &lo, float &hi) {
    asm("mov.b64 {%0,%1}, %2;" : "=f"(lo), "=f"(hi) : "l"(v));
}
__device__ __forceinline__ void fma2(ull &d, ull a, ull b) {
    asm("fma.rn.f32x2 %0, %1, %2, %0;" : "+l"(d) : "l"(a), "l"(b));
}

// --------------------- dense Lstack scratch (once) -------------------------
__global__ void k_lstack(const float* __restrict__ S) {
    int idx = blockIdx.x * blockDim.x + threadIdx.x;
    if (idx >= MST*LDK) return;
    int m = idx / LDK, n = idx % LDK;
    float v = 0.f;
    if (n < NN) {
        if (m < NN) {
            v = S[m*NN + n];
        } else {
            int mm = m - NN;
            float s = 0.f;
            for (int k = 0; k < NN; k++) s += S[mm*NN + k] * S[k*NN + n];
            v = 2.0f * s;
        }
    }
    g_L2[idx] = v;
}

// --------------------- CSR build (once per launch) -------------------------
__global__ void k_count() {
    int r = blockIdx.x * blockDim.x + threadIdx.x;
    if (r >= MST) return;
    int c = 0;
    for (int k = 0; k < NN; k++) c += (g_L2[r*LDK + k] != 0.f);
    g_cnt[r] = (c + 3) & ~3;            // pad rows to multiple of 4
}
__global__ void k_scan() {
    if (threadIdx.x == 0 && blockIdx.x == 0) {
        int s = 0;
        for (int r = 0; r < MST; r++) { g_rp[r] = s; s += g_cnt[r]; }
        g_rp[MST] = s;
    }
}
__global__ void k_fill() {
    int r = blockIdx.x * blockDim.x + threadIdx.x;
    if (r >= MST) return;
    int w = g_rp[r];
    for (int k = 0; k < NN; k++) {
        float v = g_L2[r*LDK + k];
        if (v != 0.f) { g_vals[w] = v; g_cols[w] = k; w++; }
    }
    int e = g_rp[r + 1];
    while (w < e) { g_vals[w] = 0.f; g_cols[w] = 0; w++; }
}

// ------------------------------ state init ---------------------------------
__global__ void k_zero() {
    int i = blockIdx.x * blockDim.x + threadIdx.x;
    int st = gridDim.x * blockDim.x;
    for (int j = i; j < NPADR*JHH; j += st) { g_h0[j] = 0.f; g_h1[j] = 0.f; }
    for (int j = i; j < NPADR*64;  j += st) g_din[j] = 0.f;
}

// --------------- encoder input transpose (B,N,2) -> (N, B*2) ---------------
__global__ void k_pack_enc(const float* __restrict__ x) {
    int i = blockIdx.x * blockDim.x + threadIdx.x;
    if (i >= NN*128) return;
    int n = i >> 7, c = i & 127;
    int b = c >> 1, f = c & 1;
    g_xx[i] = x[(b*NN + n)*2 + f];
}

// ------------------- sparse diffusion SpMM ---------------------------------
// For a 32-col j-tile: cache X[0..324][j0..j0+31] in smem (stride 36), then
// each (row, 4-col group) thread walks that row's CSR entries.
// grid.x = nbx (x-part j-tiles) + 128 (h-part j-tiles).
__global__ __launch_bounds__(256) void k_spmm(int axsel, int Jx, int nbx, int ahsel)
{
    __shared__ __align__(16) float Bs[NN*36];   // 46.8 KB
    const float* Ain; int J, j0; float *O1, *O2;
    int bx = blockIdx.x;
    if (bx < nbx) {
        Ain = (axsel == 0) ? g_xx : (axsel == 1) ? g_h0 : g_din;
        J = Jx; j0 = bx * 32; O1 = g_X1x; O2 = g_X2x;
    } else {
        Ain = (ahsel == 0) ? g_h0 : (ahsel == 1) ? g_h1 : g_rh;
        J = JHH; j0 = (bx - nbx) * 32; O1 = g_X1h; O2 = g_X2h;
    }
    const int tid = threadIdx.x;

    for (int idx = tid; idx < NN*8; idx += 256) {
        int r = idx >> 3, c4 = idx & 7;
        *(float4*)&Bs[r*36 + c4*4] = *(const float4*)&Ain[r*J + j0 + c4*4];
    }
    __syncthreads();

    const int rg = tid >> 3, cg = tid & 7;        // 32 row-lanes x 8 col-groups
    const int jg = j0 + cg*4;

    for (int r = rg; r < MST; r += 32) {
        int beg = g_rp[r], end = g_rp[r+1];
        ull a0 = 0, a1 = 0, a2 = 0, a3 = 0;       // 2 cols x 2-deep interleave
        for (int i = beg; i < end; i += 4) {
            int4   c4 = *(const int4*)  &g_cols[i];
            float4 v4 = *(const float4*)&g_vals[i];
            ulonglong2 b0 = *(const ulonglong2*)&Bs[c4.x*36 + cg*4];
            ulonglong2 b1 = *(const ulonglong2*)&Bs[c4.y*36 + cg*4];
            ulonglong2 b2 = *(const ulonglong2*)&Bs[c4.z*36 + cg*4];
            ulonglong2 b3 = *(const ulonglong2*)&Bs[c4.w*36 + cg*4];
            ull v0 = pk2(v4.x, v4.x), v1 = pk2(v4.y, v4.y);
            ull v2 = pk2(v4.z, v4.z), v3 = pk2(v4.w, v4.w);
            fma2(a0, v0, b0.x); fma2(a1, v0, b0.y);
            fma2(a2, v1, b1.x); fma2(a3, v1, b1.y);
            fma2(a0, v2, b2.x); fma2(a1, v2, b2.y);
            fma2(a2, v3, b3.x); fma2(a3, v3, b3.y);
        }
        float o0, o1, o2, o3, p0, p1, p2, p3;
        upk2(a0, o0, o1); upk2(a1, o2, o3);
        upk2(a2, p0, p1); upk2(a3, p2, p3);
        o0 += p0; o1 += p1; o2 += p2; o3 += p3;
        if (r < NN) {
            *(float4*)&O1[r*J + jg] = make_float4(o0, o1, o2, o3);
        } else {
            int mm = r - NN;
            float4 x0 = *(const float4*)&Ain[mm*J + jg];
            *(float4*)&O2[mm*J + jg] = make_float4(o0 - x0.x, o1 - x0.y,
                                                   o2 - x0.z, o3 - x0.w);
        }
    }
}

// --------------- weight GEMM over 6 K-segments + fused GRU epilogue --------
// A = [x | h | S@x | S@h | (2S^2-I)@x | (2S^2-I)@h] (RR x 3F), W(3F x BN).
// MODE 0 (gate, BN=128): sigmoid; o<U -> rh = r*h ; o>=U -> u.
// MODE 1 (cand, BN=64):  tanh;    h = u*h + (1-u)*c (in place).
// Block 128(r) x BN(o), 256 threads, micro 8 x (BN/16) via f32x2.
template<int BN, int MODE>
__global__ __launch_bounds__(256) void k_wg(const float* __restrict__ W,
                                            const float* __restrict__ bias,
                                            int xF, int axsel, int phsel, int uh)
{
    constexpr int TO = BN / 16;                 // o-cols per thread (8 or 4)
    __shared__ __align__(16) float As[16][132];
    __shared__ __align__(16) float Bs[16][BN];
    const float* px = (axsel == 0) ? g_xx : (axsel == 1) ? g_h0 : g_din;
    const float* ph = (phsel == 0) ? g_h0 : (phsel == 1) ? g_h1 : g_rh;
    float* h = uh ? g_h1 : g_h0;
    const int F = xF + UU;
    const int tid = threadIdx.x;
    const int r0 = blockIdx.x * 128;
    const int tx = tid & 15, ty = tid >> 4;

    ull acc[8][TO/2];
    #pragma unroll
    for (int i = 0; i < 8; i++)
        #pragma unroll
        for (int j = 0; j < TO/2; j++) acc[i][j] = 0ULL;

    #pragma unroll 1
    for (int s = 0; s < 6; s++) {
        const float* A; int K, wr;
        switch (s) {
            case 0:  A = px;     K = xF; wr = 0;        break;
            case 1:  A = ph;     K = UU; wr = xF;       break;
            case 2:  A = g_X1x;  K = xF; wr = F;        break;
            case 3:  A = g_X1h;  K = UU; wr = F + xF;   break;
            case 4:  A = g_X2x;  K = xF; wr = 2*F;      break;
            default: A = g_X2h;  K = UU; wr = 2*F + xF; break;
        }
        for (int k0 = 0; k0 < K; k0 += 16) {
            if (K == UU) {
                #pragma unroll
                for (int e = 0; e < 2; e++) {
                    int idx = tid + e*256;
                    int r = idx >> 2, kq = idx & 3;
                    int gr = r0 + r;
                    float4 v = {0.f,0.f,0.f,0.f};
                    if (gr < RR) v = *(const float4*)&A[gr*UU + k0 + kq*4];
                    As[kq*4+0][r] = v.x; As[kq*4+1][r] = v.y;
                    As[kq*4+2][r] = v.z; As[kq*4+3][r] = v.w;
                }
            } else {
                #pragma unroll
                for (int e = 0; e < 8; e++) {
                    int idx = tid + e*256;
                    int r = idx >> 4, k = idx & 15;
                    int gr = r0 + r;
                    As[k][r] = (k < K && gr < RR) ? A[gr*K + k] : 0.f;
                }
            }
            #pragma unroll
            for (int e = 0; e < BN/64; e++) {
                int idx = tid + e*256;
                int r = idx / (BN/4), c4 = idx % (BN/4);
                float4 v = {0.f,0.f,0.f,0.f};
                if (k0 + r < K) v = *(const float4*)&W[(wr + k0 + r)*BN + c4*4];
                *(float4*)&Bs[r][c4*4] = v;
            }
            __syncthreads();
            #pragma unroll
            for (int k = 0; k < 16; k++) {
                float4 alo = *(const float4*)&As[k][ty*8];
                float4 ahi = *(const float4*)&As[k][ty*8 + 4];
                ull b[TO/2];
                {
                    ulonglong2 q0 = *(const ulonglong2*)&Bs[k][tx*TO];
                    b[0] = q0.x; b[1] = q0.y;
                    if (TO == 8) {
                        ulonglong2 q1 = *(const ulonglong2*)&Bs[k][tx*TO + 4];
                        b[TO/2 - 2] = q1.x; b[TO/2 - 1] = q1.y;
                    }
                }
                float av[8] = {alo.x, alo.y, alo.z, alo.w,
                               ahi.x, ahi.y, ahi.z, ahi.w};
                #pragma unroll
                for (int i = 0; i < 8; i++) {
                    ull ap = pk2(av[i], av[i]);
                    #pragma unroll
                    for (int j = 0; j < TO/2; j++) fma2(acc[i][j], ap, b[j]);
                }
            }
            __syncthreads();
        }
    }

    #pragma unroll
    for (int i = 0; i < 8; i++) {
        int r = r0 + ty*8 + i;
        if (r >= RR) continue;
        #pragma unroll
        for (int j = 0; j < TO/2; j++) {
            float lo, hi; upk2(acc[i][j], lo, hi);
            #pragma unroll
            for (int p = 0; p < 2; p++) {
                int og = tx*TO + 2*j + p;
                float v = (p ? hi : lo) + bias[og];
                if (MODE == 0) {
                    float sg = 1.0f / (1.0f + expf(-v));
                    if (og < UU) g_rh[r*UU + og] = sg * h[r*UU + og];
                    else         g_u [r*UU + og - UU] = sg;
                } else {
                    float c = tanhf(v);
                    int idx2 = r*UU + og;
                    float u = g_u[idx2];
                    h[idx2] = u * h[idx2] + (1.0f - u) * c;
                }
            }
        }
    }
}

// --------- projection: out[b*N+n] = h1[n,b,:] . pW + pb; also -> g_din -----
__global__ void k_proj(const float* __restrict__ pW, const float* __restrict__ pb,
                       float* __restrict__ outp) {
    int gid = blockIdx.x * blockDim.x + threadIdx.x;
    int row = gid >> 5, lane = gid & 31;
    if (row >= RR) return;
    float s = g_h1[row*UU + lane] * pW[lane]
            + g_h1[row*UU + lane + 32] * pW[lane + 32];
    #pragma unroll
    for (int off = 16; off; off >>= 1) s += __shfl_down_sync(0xffffffffu, s, off);
    if (lane == 0) {
        float v = s + pb[0];
        int n = row / BB, b = row % BB;
        outp[b*NN + n] = v;
        g_din[row] = v;
    }
}

// ------------------------------- host side ---------------------------------
static void run_cell(int xF, int axsel, int uh,
                     const float* gW, const float* gb,
                     const float* cW, const float* cb) {
    int Jx  = BB * xF;
    int nbx = Jx / 32;                 // 4 (enc L0), 2 (dec L0), 128 (L1)
    // gate: diffuse x-part + h-part, then gate GEMM
    k_spmm<<<nbx + 128, 256>>>(axsel, Jx, nbx, uh);
    k_wg<128,0><<<WGB, 256>>>(gW, gb, xF, axsel, uh, uh);
    // candidate: diffuse only r*h (x diffusion reused), then cand GEMM
    k_spmm<<<128, 256>>>(0, 0, 0, /*ahsel=rh*/2);
    k_wg<64,1><<<WGB, 256>>>(cW, cb, xF, axsel, 2, uh);
}

extern "C" void kernel_launch(void* const* d_in, const int* in_sizes, int n_in,
                              void* d_out, int out_size) {
    const float* inputs  = (const float*)d_in[0];
    const float* support = (const float*)d_in[1];
    const float* W[16];
    for (int i = 0; i < 16; i++) W[i] = (const float*)d_in[2 + i];
    const float* projW = (const float*)d_in[18];
    const float* projb = (const float*)d_in[19];
    float* out = (float*)d_out;

    k_lstack<<<(MST*LDK + 255) / 256, 256>>>(support);
    k_count <<<(MST + 255) / 256, 256>>>();
    k_scan  <<<1, 32>>>();
    k_fill  <<<(MST + 255) / 256, 256>>>();
    k_zero  <<<592, 256>>>();

    for (int t = 0; t < TSTEPS; t++) {
        k_pack_enc<<<(NN*128 + 255) / 256, 256>>>(inputs + (size_t)t * BB * NN * 2);
        run_cell(2,  /*x=g_xx*/0, /*h=*/0, W[0],  W[1],  W[2],  W[3]);   // enc L0
        run_cell(64, /*x=g_h0*/1, /*h=*/1, W[4],  W[5],  W[6],  W[7]);   // enc L1
    }
    for (int t = 0; t < HSTEPS; t++) {
        run_cell(1,  /*x=din*/2,  /*h=*/0, W[8],  W[9],  W[10], W[11]);  // dec L0
        run_cell(64, /*x=g_h0*/1, /*h=*/1, W[12], W[13], W[14], W[15]);  // dec L1
        k_proj<<<(RR*32 + 255) / 256, 256>>>(projW, projb, out + (size_t)t * BB * NN);
    }
}